// round 3
// baseline (speedup 1.0000x reference)
#include <cuda_runtime.h>
#include <math.h>

#define NN 4096
#define DD 256
#define SS 32
#define KK 4
#define KS (KK*SS)      // 128
#define CHUNK 64
#define ZROW 132        // padded szc row (floats), 16B-aligned, low-conflict
#define ETA 0.5f

// ---------------- device scratch (no allocations allowed) ----------------
__device__ float g_Z[KK * NN * SS];   // Z[k][n][s], 2 MB
__device__ float g_Ut[KS * DD];       // Ut[(k*S+s)][d], 128 KB
__device__ float g_O[NN * KS];        // normalized per-head outputs, 2 MB
__device__ float g_orth_partial[10];

// ---------------- kernel 1: transpose U [K,D,S] -> Ut [K*S, D] ----------------
__global__ void k_transU(const float* __restrict__ U) {
    int idx = blockIdx.x * 256 + threadIdx.x;
    if (idx < KK * DD * SS) {
        int k = idx / (DD * SS);
        int r = idx % (DD * SS);
        int d = r / SS;
        int s = r % SS;
        g_Ut[(k * SS + s) * DD + d] = U[idx];
    }
}

// ---------------- kernel 2: Z[k][n][s] = sum_d H[n][d] * U[k][d][s] ----------------
__global__ __launch_bounds__(128) void k_Z(const float* __restrict__ H,
                                           const float* __restrict__ U) {
    __shared__ float Hs[16 * DD];          // 16 KB
    const int row0 = blockIdx.x * 16;
    const int tid  = threadIdx.x;

    const float4* Hg = (const float4*)(H + (size_t)row0 * DD);
    float4* Hs4 = (float4*)Hs;
    for (int idx = tid; idx < 16 * DD / 4; idx += 128) Hs4[idx] = Hg[idx];
    __syncthreads();

    const int k = tid >> 5, s = tid & 31;
    float acc[16];
#pragma unroll
    for (int r = 0; r < 16; r++) acc[r] = 0.f;

    const float* Uk = U + (size_t)k * DD * SS + s;   // U[k][d][s], stride S
    for (int d = 0; d < DD; d++) {
        float u = __ldg(Uk + d * SS);
#pragma unroll
        for (int r = 0; r < 16; r++) acc[r] += Hs[r * DD + d] * u;
    }
#pragma unroll
    for (int r = 0; r < 16; r++)
        g_Z[((size_t)k * NN + row0 + r) * SS + s] = acc[r];
}

// ---------------- kernel 3: per-row sparse flash attention over all 4 heads ----------------
// grid = 4096 blocks (one row each), 256 threads.
__global__ __launch_bounds__(256) void k_attn(const float* __restrict__ adj,
                                              const float* __restrict__ lp) {
    const int i   = blockIdx.x;
    const int tid = threadIdx.x;
    const int wid = tid >> 5, lane = tid & 31;

    __shared__ unsigned short nbr[NN];       // 8 KB
    __shared__ float szc[CHUNK * ZROW];      // 33 KB gathered-Z cache
    __shared__ float sc[KK][CHUNK];          // 1 KB probs
    __shared__ float so[KS];
    __shared__ float zsi[KS];
    __shared__ float sm[4], sl[4], sscale[4], cmax[4];
    __shared__ float wred[8 * 4];
    __shared__ int wcnt[8], woff[8];
    __shared__ int s_count;

    const float NEG_INF = __int_as_float(0xff800000);

    if (tid < KS) {
        float z = g_Z[((size_t)(tid >> 5) * NN + i) * SS + (tid & 31)];
        zsi[tid] = z * __expf(lp[tid]);
        so[tid]  = 0.f;
    }
    if (tid < 4) { sm[tid] = NEG_INF; sl[tid] = 0.f; }
    if (tid == 0) s_count = 0;
    __syncthreads();

    // ---- phase A: deterministic ordered compaction, float4 reads ----
    const float4* row4 = (const float4*)(adj + (size_t)i * NN);
    for (int it = 0; it < NN / 1024; it++) {
        const int base = it * 1024;
        float4 v = __ldg(row4 + (base >> 2) + tid);
        int f0 = v.x > 0.5f, f1 = v.y > 0.5f, f2 = v.z > 0.5f, f3 = v.w > 0.5f;
        int cnt = f0 + f1 + f2 + f3;

        int scan = cnt;
#pragma unroll
        for (int o = 1; o < 32; o <<= 1) {
            int u = __shfl_up_sync(0xffffffffu, scan, o);
            if (lane >= o) scan += u;
        }
        if (lane == 31) wcnt[wid] = scan;
        __syncthreads();
        if (tid == 0) {
            int acc = s_count;
#pragma unroll
            for (int w = 0; w < 8; w++) { woff[w] = acc; acc += wcnt[w]; }
            s_count = acc;
        }
        __syncthreads();
        int pos = woff[wid] + scan - cnt;
        const int e = base + tid * 4;
        if (f0) nbr[pos++] = (unsigned short)(e);
        if (f1) nbr[pos++] = (unsigned short)(e + 1);
        if (f2) nbr[pos++] = (unsigned short)(e + 2);
        if (f3) nbr[pos]   = (unsigned short)(e + 3);
    }
    __syncthreads();
    const int count = s_count;
    const float inv_sqrt_s = rsqrtf((float)SS);

    // ---- phase B: flash softmax over 64-neighbor chunks, 4 heads at once ----
    const int jl   = tid >> 2;     // local neighbor index 0..63
    const int head = tid & 3;

    for (int c0 = 0; c0 < count; c0 += CHUNK) {
        const int clen = min(CHUNK, count - c0);

        // gather Z chunk + scores; cache gathered values in smem
        if (jl < clen) {
            const int j = nbr[c0 + jl];
            const float4* zp = (const float4*)(g_Z + ((size_t)head * NN + j) * SS);
            const float*  zs = zsi + head * 32;
            float4 vv[8];
#pragma unroll
            for (int q = 0; q < 8; q++) vv[q] = __ldg(zp + q);
            float dot = 0.f;
            float4* dst = (float4*)(szc + jl * ZROW + head * 32);
#pragma unroll
            for (int q = 0; q < 8; q++) {
                dot += zs[4*q] * vv[q].x + zs[4*q+1] * vv[q].y
                     + zs[4*q+2] * vv[q].z + zs[4*q+3] * vv[q].w;
                dst[q] = vv[q];
            }
            sc[head][jl] = dot * inv_sqrt_s;
        }
        __syncthreads();

        // per-head chunk max (warps 0..3)
        if (wid < 4) {
            float mx = NEG_INF;
            for (int t = lane; t < clen; t += 32) mx = fmaxf(mx, sc[wid][t]);
#pragma unroll
            for (int o = 16; o > 0; o >>= 1)
                mx = fmaxf(mx, __shfl_xor_sync(0xffffffffu, mx, o));
            if (lane == 0) cmax[wid] = mx;
        }
        __syncthreads();
        if (tid < 4) {
            float mo = sm[tid];
            float mn = fmaxf(mo, cmax[tid]);
            float sca = (mo < -1e37f) ? 0.f : __expf(mo - mn);
            sm[tid] = mn; sscale[tid] = sca; sl[tid] *= sca;
        }
        __syncthreads();
        if (tid < KS) so[tid] *= sscale[tid >> 5];

        // exponentiate + per-thread partial sums (thread handles its (jl,head) slot)
        float p = 0.f;
        if (jl < clen) {
            float e = __expf(sc[head][jl] - sm[head]);
            sc[head][jl] = e;
            p = e;
        }
        // reduce p per head: lanes of a warp cover 8 neighbors x 4 heads.
        // sum within warp over lanes with the same head (stride-4 pattern).
#pragma unroll
        for (int o = 16; o >= 4; o >>= 1)
            p += __shfl_xor_sync(0xffffffffu, p, o);
        if (lane < 4) wred[wid * 4 + lane] = p;   // lane==head here
        __syncthreads();
        if (tid < 4) {
            float a = sl[tid];
            for (int w = 0; w < 8; w++) a += wred[w * 4 + tid];
            sl[tid] = a;
        }

        // accumulate outputs from the smem cache: thread (k,s) += sum_j p[j][k]*Zc[j][k][s]
        if (tid < KS) {
            const int k = tid >> 5, s = tid & 31;
            float acc = so[tid];
            const float* zb = szc + k * 32 + s;
            int t2 = 0;
            for (; t2 + 3 < clen; t2 += 4) {
                acc += sc[k][t2]     * zb[(t2)     * ZROW]
                     + sc[k][t2 + 1] * zb[(t2 + 1) * ZROW]
                     + sc[k][t2 + 2] * zb[(t2 + 2) * ZROW]
                     + sc[k][t2 + 3] * zb[(t2 + 3) * ZROW];
            }
            for (; t2 < clen; t2++)
                acc += sc[k][t2] * zb[t2 * ZROW];
            so[tid] = acc;
        }
        __syncthreads();
    }

    if (tid < KS)
        g_O[(size_t)i * KS + tid] = so[tid] / sl[tid >> 5];
}

// ---------------- kernel 4: projection + epilogue ----------------
__global__ __launch_bounds__(256) void k_proj(const float* __restrict__ H,
                                              const float* __restrict__ thr,
                                              float* __restrict__ out) {
    __shared__ float sO[32 * KS];            // 16 KB
    const int r0  = blockIdx.x * 32;
    const int tid = threadIdx.x;

    const float4* Og = (const float4*)(g_O + (size_t)r0 * KS);
    float4* sO4 = (float4*)sO;
    for (int idx = tid; idx < 32 * KS / 4; idx += 256) sO4[idx] = Og[idx];
    __syncthreads();

    const int d = tid;
    float acc[32];
#pragma unroll
    for (int r = 0; r < 32; r++) acc[r] = 0.f;

    for (int t = 0; t < KS; t++) {
        float u = __ldg(g_Ut + t * DD + d);
#pragma unroll
        for (int r = 0; r < 32; r++) acc[r] += sO[r * KS + t] * u;
    }

    const float tthr = thr[d];
#pragma unroll 4
    for (int r = 0; r < 32; r++) {
        float h = H[(size_t)(r0 + r) * DD + d] + ETA * acc[r];
        float a = fabsf(h) - tthr;
        out[(size_t)(r0 + r) * DD + d] = (a > 0.f) ? copysignf(a, h) : 0.f;
    }
}

// ---------------- kernel 5: orthogonality loss ----------------
__global__ __launch_bounds__(1024) void k_orth() {
    const int pk[10] = {0,0,0,0,1,1,1,2,2,3};
    const int pl[10] = {0,1,2,3,1,2,3,2,3,3};
    const int k = pk[blockIdx.x], l = pl[blockIdx.x];

    __shared__ float tA[32 * 32];
    __shared__ float tB[32 * 33];
    __shared__ float ws[32];

    const int tid = threadIdx.x;
    const int a = tid >> 5, b = tid & 31;
    float c = 0.f;

    for (int d0 = 0; d0 < DD; d0 += 32) {
        int ra = tid >> 5, dc = tid & 31;
        tA[ra * 32 + dc] = g_Ut[(k * SS + ra) * DD + d0 + dc];
        tB[ra * 33 + dc] = g_Ut[(l * SS + ra) * DD + d0 + dc];
        __syncthreads();
#pragma unroll
        for (int dc2 = 0; dc2 < 32; dc2++)
            c += tA[a * 32 + dc2] * tB[b * 33 + dc2];
        __syncthreads();
    }

    float val;
    if (k == l) { float e = (a == b) ? (c - 1.f) : c; val = e * e; }
    else        { val = c * c; }

#pragma unroll
    for (int o = 16; o > 0; o >>= 1) val += __shfl_xor_sync(0xffffffffu, val, o);
    if ((tid & 31) == 0) ws[tid >> 5] = val;
    __syncthreads();
    if (tid < 32) {
        float v = ws[tid];
#pragma unroll
        for (int o = 16; o > 0; o >>= 1) v += __shfl_xor_sync(0xffffffffu, v, o);
        if (tid == 0) g_orth_partial[blockIdx.x] = v;
    }
}

__global__ void k_orth_sum(float* __restrict__ out) {
    float s = 0.f;
    for (int i = 0; i < 10; i++) s += g_orth_partial[i];
    out[(size_t)NN * DD] = s;
}

// ---------------- launch ----------------
extern "C" void kernel_launch(void* const* d_in, const int* in_sizes, int n_in,
                              void* d_out, int out_size) {
    const float* H   = (const float*)d_in[0];
    const float* adj = (const float*)d_in[1];
    const float* U   = (const float*)d_in[2];
    const float* lp  = (const float*)d_in[3];
    const float* thr = (const float*)d_in[4];
    float* out = (float*)d_out;

    k_transU<<<(KK * DD * SS + 255) / 256, 256>>>(U);
    k_Z<<<NN / 16, 128>>>(H, U);
    k_attn<<<NN, 256>>>(adj, lp);
    k_proj<<<NN / 32, 256>>>(H, thr, out);
    if (out_size > NN * DD) {
        k_orth<<<10, 1024>>>();
        k_orth_sum<<<1, 1>>>(out);
    }
}

// round 9
// speedup vs baseline: 1.4224x; 1.4224x over previous
#include <cuda_runtime.h>
#include <math.h>

#define NN 4096
#define DD 256
#define SS 32
#define KK 4
#define KS (KK*SS)      // 128
#define CHUNK 64
#define ZROW 144        // szc row stride (floats); reads conflict-free (16t+4k+s)
#define HOFF 36
#define ETA 0.5f

// ---------------- device scratch (no allocations allowed) ----------------
__device__ float g_Z[KK * NN * SS];   // Z[k][n][s], 2 MB
__device__ float g_Ut[KS * DD];       // Ut[(k*S+s)][d], 128 KB
__device__ float g_O[NN * KS];        // normalized per-head outputs, 2 MB
__device__ float g_orth_partial[10];

// ---------------- kernel 1: transpose U [K,D,S] -> Ut [K*S, D] ----------------
__global__ void k_transU(const float* __restrict__ U) {
    int idx = blockIdx.x * 256 + threadIdx.x;
    if (idx < KK * DD * SS) {
        int k = idx / (DD * SS);
        int r = idx % (DD * SS);
        int d = r / SS;
        int s = r % SS;
        g_Ut[(k * SS + s) * DD + d] = U[idx];
    }
}

// ---------------- kernel 2: Z[k][n][s] = sum_d H[n][d] * U[k][d][s] ----------------
// grid 512 blocks x 128 threads; 8 rows per block; thread = one (k,s) column.
__global__ __launch_bounds__(128) void k_Z(const float* __restrict__ H,
                                           const float* __restrict__ U) {
    __shared__ float Hs[8 * DD];           // 8 KB
    const int row0 = blockIdx.x * 8;
    const int tid  = threadIdx.x;

    const float4* Hg = (const float4*)(H + (size_t)row0 * DD);
    float4* Hs4 = (float4*)Hs;
    for (int idx = tid; idx < 8 * DD / 4; idx += 128) Hs4[idx] = Hg[idx];
    __syncthreads();

    const int k = tid >> 5, s = tid & 31;
    float acc[8];
#pragma unroll
    for (int r = 0; r < 8; r++) acc[r] = 0.f;

    const float* Uk = U + (size_t)k * DD * SS + s;   // U[k][d][s]; lanes coalesce per d
#pragma unroll 4
    for (int d = 0; d < DD; d++) {
        float u = __ldg(Uk + d * SS);
#pragma unroll
        for (int r = 0; r < 8; r++) acc[r] += Hs[r * DD + d] * u;
    }
#pragma unroll
    for (int r = 0; r < 8; r++)
        g_Z[((size_t)k * NN + row0 + r) * SS + s] = acc[r];
}

// ---------------- kernel 3: per-row sparse flash attention, 4 heads at once ----------
// grid = 4096 blocks (one row each), 256 threads, 4 blocks/SM.
__global__ __launch_bounds__(256, 4) void k_attn(const float* __restrict__ adj,
                                                 const float* __restrict__ lp) {
    const int i    = blockIdx.x;
    const int tid  = threadIdx.x;
    const int wid  = tid >> 5, lane = tid & 31;

    __shared__ unsigned short nbr[NN];        // 8 KB
    __shared__ float szc[CHUNK * ZROW];       // 36 KB gathered-Z cache (swizzled)
    __shared__ float sc[KK][CHUNK];           // 1 KB probs
    __shared__ float so_odd[KS];              // odd-half accumulators at the end
    __shared__ float zsi[KS];
    __shared__ float sm[4], sl[4], sscale[4];
    __shared__ float wred[8 * 4];
    __shared__ float wmax[8 * 4];
    __shared__ int wcnt[8], woff[8];
    __shared__ int s_count;

    const float NEG_INF = __int_as_float(0xff800000);

    // prefetch the mask slice FIRST so the DRAM round-trip overlaps init
    const float4* row4 = (const float4*)(adj + (size_t)i * NN);
    float4 a[4];
#pragma unroll
    for (int q = 0; q < 4; q++) a[q] = __ldg(row4 + tid * 4 + q);

    if (tid < KS) {
        float z = g_Z[((size_t)(tid >> 5) * NN + i) * SS + (tid & 31)];
        zsi[tid] = z * __expf(lp[tid]);
    }
    if (tid < 4) { sm[tid] = NEG_INF; sl[tid] = 0.f; }

    // ---- phase A: one-shot deterministic compaction ----
    unsigned m16 = 0;
#pragma unroll
    for (int q = 0; q < 4; q++) {
        if (((const float*)&a[q])[0] > 0.5f) m16 |= 1u << (4 * q + 0);
        if (((const float*)&a[q])[1] > 0.5f) m16 |= 1u << (4 * q + 1);
        if (((const float*)&a[q])[2] > 0.5f) m16 |= 1u << (4 * q + 2);
        if (((const float*)&a[q])[3] > 0.5f) m16 |= 1u << (4 * q + 3);
    }
    {
        int cnt = __popc(m16);
        int scan = cnt;
#pragma unroll
        for (int o = 1; o < 32; o <<= 1) {
            int u = __shfl_up_sync(0xffffffffu, scan, o);
            if (lane >= o) scan += u;
        }
        if (lane == 31) wcnt[wid] = scan;
        __syncthreads();
        if (wid == 0 && lane < 8) {
            int c = wcnt[lane];
            int sc2 = c;
#pragma unroll
            for (int o = 1; o < 8; o <<= 1) {
                int u = __shfl_up_sync(0xffu, sc2, o);
                if (lane >= o) sc2 += u;
            }
            woff[lane] = sc2 - c;
            if (lane == 7) s_count = sc2;
        }
        __syncthreads();
        int pos = woff[wid] + scan - cnt;
        unsigned m = m16;
        while (m) {
            int e = __ffs(m) - 1;
            m &= m - 1;
            nbr[pos++] = (unsigned short)(tid * 16 + e);
        }
    }
    __syncthreads();
    const int count = s_count;
    const float inv_sqrt_s = rsqrtf((float)SS);

    // ---- phase B: flash softmax over 64-neighbor chunks (4 barriers/chunk) ----
    const int jl   = tid >> 2;     // local neighbor index 0..63
    const int head = tid & 3;
    const int k    = (tid >> 5) & 3;   // accumulate role: (k, s, half)
    const int s    = tid & 31;
    const int half = tid >> 7;         // 0: even t, 1: odd t
    float accR = 0.f;

    for (int c0 = 0; c0 < count; c0 += CHUNK) {
        const int clen = min(CHUNK, count - c0);

        // 1. gather Z chunk, score in register, cache swizzled in smem
        float scored = NEG_INF;
        if (jl < clen) {
            const int j = nbr[c0 + jl];
            const float4* zp = (const float4*)(g_Z + ((size_t)head * NN + j) * SS);
            const float*  zs = zsi + head * 32;
            float4 vv[8];
#pragma unroll
            for (int q = 0; q < 8; q++) vv[q] = __ldg(zp + q);
            float dot = 0.f;
            float4* dst = (float4*)(szc + jl * ZROW + head * HOFF);
#pragma unroll
            for (int q = 0; q < 8; q++) {
                dot += zs[4*q] * vv[q].x + zs[4*q+1] * vv[q].y
                     + zs[4*q+2] * vv[q].z + zs[4*q+3] * vv[q].w;
                dst[q] = vv[q];
            }
            scored = dot * inv_sqrt_s;
        }
        // warp max per head (stride-4 groups)
        float mx = scored;
#pragma unroll
        for (int o = 16; o >= 4; o >>= 1)
            mx = fmaxf(mx, __shfl_xor_sync(0xffffffffu, mx, o));
        if (lane < 4) wmax[wid * 4 + lane] = mx;
        __syncthreads();                                   // (1)

        // 2. softmax state update (threads 0..3, one head each)
        if (tid < 4) {
            float cm = wmax[tid];
#pragma unroll
            for (int w = 1; w < 8; w++) cm = fmaxf(cm, wmax[w * 4 + tid]);
            float mo = sm[tid];
            float mn = fmaxf(mo, cm);
            float sca = (mo < -1e37f) ? 0.f : __expf(mo - mn);
            sm[tid] = mn; sscale[tid] = sca; sl[tid] *= sca;
        }
        __syncthreads();                                   // (2)

        // 3. exponentiate (register score), partial sums via shuffle
        float p = 0.f;
        if (jl < clen) {
            p = __expf(scored - sm[head]);
            sc[head][jl] = p;
        }
        float ps = p;
#pragma unroll
        for (int o = 16; o >= 4; o >>= 1)
            ps += __shfl_xor_sync(0xffffffffu, ps, o);
        if (lane < 4) wred[wid * 4 + lane] = ps;
        accR *= sscale[k];          // rescale running output (register)
        __syncthreads();                                   // (3)

        // 4. finalize l; accumulate outputs from smem cache (split even/odd t)
        if (tid < 4) {
            float a2 = sl[tid];
#pragma unroll
            for (int w = 0; w < 8; w++) a2 += wred[w * 4 + tid];
            sl[tid] = a2;
        }
        {
            const float* zb = szc + k * HOFF + s;
            int t = half;
            for (; t + 2 < clen; t += 4) {
                float v0 = zb[t * ZROW];
                float v1 = zb[(t + 2) * ZROW];
                accR += sc[k][t] * v0 + sc[k][t + 2] * v1;
            }
            for (; t < clen; t += 2)
                accR += sc[k][t] * zb[t * ZROW];
        }
        __syncthreads();                                   // (4) protects szc/sc reuse
    }

    // combine halves and write normalized output
    if (half == 1) so_odd[tid - 128] = accR;
    __syncthreads();
    if (half == 0)
        g_O[(size_t)i * KS + tid] = (accR + so_odd[tid]) / sl[k];
}

// ---------------- kernel 4: projection + epilogue ----------------
// grid 512 blocks x 256 threads; 8 rows per block (acc[8] stays in registers).
__global__ __launch_bounds__(256) void k_proj(const float* __restrict__ H,
                                              const float* __restrict__ thr,
                                              float* __restrict__ out) {
    __shared__ float sO[8 * KS];             // 4 KB
    const int r0  = blockIdx.x * 8;
    const int tid = threadIdx.x;

    ((float4*)sO)[tid] = ((const float4*)(g_O + (size_t)r0 * KS))[tid];

    const int d = tid;
    // prefetch H rows so their latency overlaps the dot-product loop
    float hreg[8];
#pragma unroll
    for (int r = 0; r < 8; r++) hreg[r] = H[(size_t)(r0 + r) * DD + d];
    const float tthr = thr[d];
    __syncthreads();

    float acc[8];
#pragma unroll
    for (int r = 0; r < 8; r++) acc[r] = 0.f;

#pragma unroll 4
    for (int t = 0; t < KS; t++) {
        float u = __ldg(g_Ut + t * DD + d);
#pragma unroll
        for (int r = 0; r < 8; r++) acc[r] += sO[r * KS + t] * u;
    }

#pragma unroll
    for (int r = 0; r < 8; r++) {
        float h = hreg[r] + ETA * acc[r];
        float a = fabsf(h) - tthr;
        out[(size_t)(r0 + r) * DD + d] = (a > 0.f) ? copysignf(a, h) : 0.f;
    }
}

// ---------------- kernel 5: orthogonality loss ----------------
__global__ __launch_bounds__(1024) void k_orth() {
    const int pk[10] = {0,0,0,0,1,1,1,2,2,3};
    const int pl[10] = {0,1,2,3,1,2,3,2,3,3};
    const int k = pk[blockIdx.x], l = pl[blockIdx.x];

    __shared__ float tA[32 * 32];
    __shared__ float tB[32 * 33];
    __shared__ float ws[32];

    const int tid = threadIdx.x;
    const int a = tid >> 5, b = tid & 31;
    float c = 0.f;

    for (int d0 = 0; d0 < DD; d0 += 32) {
        int ra = tid >> 5, dc = tid & 31;
        tA[ra * 32 + dc] = g_Ut[(k * SS + ra) * DD + d0 + dc];
        tB[ra * 33 + dc] = g_Ut[(l * SS + ra) * DD + d0 + dc];
        __syncthreads();
#pragma unroll
        for (int dc2 = 0; dc2 < 32; dc2++)
            c += tA[a * 32 + dc2] * tB[b * 33 + dc2];
        __syncthreads();
    }

    float val;
    if (k == l) { float e = (a == b) ? (c - 1.f) : c; val = e * e; }
    else        { val = c * c; }

#pragma unroll
    for (int o = 16; o > 0; o >>= 1) val += __shfl_xor_sync(0xffffffffu, val, o);
    if ((tid & 31) == 0) ws[tid >> 5] = val;
    __syncthreads();
    if (tid < 32) {
        float v = ws[tid];
#pragma unroll
        for (int o = 16; o > 0; o >>= 1) v += __shfl_xor_sync(0xffffffffu, v, o);
        if (tid == 0) g_orth_partial[blockIdx.x] = v;
    }
}

__global__ void k_orth_sum(float* __restrict__ out) {
    float s = 0.f;
    for (int i = 0; i < 10; i++) s += g_orth_partial[i];
    out[(size_t)NN * DD] = s;
}

// ---------------- launch ----------------
extern "C" void kernel_launch(void* const* d_in, const int* in_sizes, int n_in,
                              void* d_out, int out_size) {
    const float* H   = (const float*)d_in[0];
    const float* adj = (const float*)d_in[1];
    const float* U   = (const float*)d_in[2];
    const float* lp  = (const float*)d_in[3];
    const float* thr = (const float*)d_in[4];
    float* out = (float*)d_out;

    k_transU<<<(KK * DD * SS + 255) / 256, 256>>>(U);
    k_Z<<<NN / 8, 128>>>(H, U);
    k_attn<<<NN, 256>>>(adj, lp);
    k_proj<<<NN / 8, 256>>>(H, thr, out);
    if (out_size > NN * DD) {
        k_orth<<<10, 1024>>>();
        k_orth_sum<<<1, 1>>>(out);
    }
}

// round 11
// speedup vs baseline: 2.1250x; 1.4939x over previous
#include <cuda_runtime.h>
#include <math.h>

#define NN 4096
#define DD 256
#define SS 32
#define KK 4
#define KS (KK*SS)      // 128
#define CHUNK 64
#define ZROW 132        // szc row stride (floats): 128 data + 4 pad; accumulate reads conflict-free
#define ETA 0.5f
#define NPROJ (NN/8)    // 512 projection blocks

// ---------------- device scratch (no allocations allowed) ----------------
__device__ float g_Z[KK * NN * SS];    // Z[k][n][s], 2 MB
__device__ float g_Ut[KS * DD];        // Ut[t][d] (orth loss)
__device__ float g_Ut4[KS * DD];       // packed: [(t>>2)*DD + d]*4 + (t&3) (proj GEMM)
__device__ float g_O[NN * KS];         // normalized per-head outputs, 2 MB
__device__ float g_orth_partial[10];

// ---------------- mbarrier / bulk-copy helpers ----------------
__device__ __forceinline__ unsigned smem_u32(const void* p) {
    return (unsigned)__cvta_generic_to_shared(p);
}
__device__ __forceinline__ void mbar_init(unsigned addr, unsigned count) {
    asm volatile("mbarrier.init.shared.b64 [%0], %1;" :: "r"(addr), "r"(count) : "memory");
}
__device__ __forceinline__ void mbar_expect_tx(unsigned addr, unsigned bytes) {
    asm volatile("mbarrier.arrive.expect_tx.shared.b64 _, [%0], %1;"
                 :: "r"(addr), "r"(bytes) : "memory");
}
__device__ __forceinline__ void bulk_ld(unsigned dst, const void* src, unsigned bytes, unsigned mbar) {
    asm volatile("cp.async.bulk.shared::cta.global.mbarrier::complete_tx::bytes [%0], [%1], %2, [%3];"
                 :: "r"(dst), "l"(src), "r"(bytes), "r"(mbar) : "memory");
}
__device__ __forceinline__ void mbar_wait(unsigned addr, unsigned parity) {
    asm volatile(
        "{\n\t.reg .pred P1;\n"
        "WAIT_%=:\n\t"
        "mbarrier.try_wait.parity.acquire.cta.shared::cta.b64 P1, [%0], %1, 0x989680;\n\t"
        "@P1 bra DONE_%=;\n\t"
        "bra WAIT_%=;\n"
        "DONE_%=:\n\t}"
        :: "r"(addr), "r"(parity) : "memory");
}

// ---------------- kernel 1: Z = H @ U  (+ folded Ut / Ut4 transpose) ----------------
// grid 512 blocks x 128 threads; 8 rows per block; thread = one (k,s) column.
__global__ __launch_bounds__(128) void k_Z(const float* __restrict__ H,
                                           const float* __restrict__ U) {
    __shared__ float Hs[8 * DD];           // 8 KB
    const int row0 = blockIdx.x * 8;
    const int tid  = threadIdx.x;

    // folded transpose: 64 U elements per block -> g_Ut and g_Ut4
    if (tid < 64) {
        int e = blockIdx.x * 64 + tid;     // e < 32768
        int k = e / (DD * SS);
        int r = e % (DD * SS);
        int d = r / SS;
        int s = r % SS;
        float v = U[e];
        int t = k * SS + s;
        g_Ut[t * DD + d] = v;
        g_Ut4[((t >> 2) * DD + d) * 4 + (t & 3)] = v;
    }

    const float4* Hg = (const float4*)(H + (size_t)row0 * DD);
    float4* Hs4 = (float4*)Hs;
    for (int idx = tid; idx < 8 * DD / 4; idx += 128) Hs4[idx] = Hg[idx];
    __syncthreads();

    const int k = tid >> 5, s = tid & 31;
    float acc[8];
#pragma unroll
    for (int r = 0; r < 8; r++) acc[r] = 0.f;

    const float* Uk = U + (size_t)k * DD * SS + s;   // lanes coalesce per d
#pragma unroll 4
    for (int d = 0; d < DD; d++) {
        float u = __ldg(Uk + d * SS);
#pragma unroll
        for (int r = 0; r < 8; r++) acc[r] += Hs[r * DD + d] * u;
    }
#pragma unroll
    for (int r = 0; r < 8; r++)
        g_Z[((size_t)k * NN + row0 + r) * SS + s] = acc[r];
}

// ---------------- kernel 2: per-row sparse flash attention, 4 heads at once ----------
// grid = 4096 blocks, 256 threads, 4 blocks/SM. Mask via TMA bulk; cooperative gather.
__global__ __launch_bounds__(256, 4) void k_attn(const float* __restrict__ adj,
                                                 const float* __restrict__ lp) {
    const int i    = blockIdx.x;
    const int tid  = threadIdx.x;
    const int wid  = tid >> 5, lane = tid & 31;

    __shared__ __align__(16) float ubuf[CHUNK * ZROW];  // 33792 B: maskbuf (16KB) then szc
    __shared__ unsigned short nbr[NN];                  // 8 KB
    __shared__ float sc[KK][68];                        // scores/probs (padded)
    __shared__ float so_odd[KS];
    __shared__ float zsi[KS];
    __shared__ float sm[4], sl[4], sscale[4];
    __shared__ float wred[8 * 4];
    __shared__ float wmax[8 * 4];
    __shared__ int wcnt[8], woff[8];
    __shared__ int s_count;
    __shared__ __align__(8) unsigned long long mbar_store;

    const float NEG_INF = __int_as_float(0xff800000);
    const unsigned mb  = smem_u32(&mbar_store);
    const unsigned ubA = smem_u32(ubuf);

    if (tid == 0) mbar_init(mb, 1);
    __syncthreads();
    if (tid == 0) {
        mbar_expect_tx(mb, NN * 4);                     // 16384 bytes
        bulk_ld(ubA, adj + (size_t)i * NN, NN * 4, mb);
    }

    // init overlaps the bulk copy
    if (tid < KS) {
        float z = g_Z[((size_t)(tid >> 5) * NN + i) * SS + (tid & 31)];
        zsi[tid] = z * __expf(lp[tid]);
    }
    if (tid < 4) { sm[tid] = NEG_INF; sl[tid] = 0.f; }

    mbar_wait(mb, 0);

    // ---- phase A: compaction from smem mask ----
    // thread owns elements e(q,c) = q*1024 + tid*4 + c  (fixed deterministic order)
    float4 av[4];
    const float4* mb4 = (const float4*)ubuf;
#pragma unroll
    for (int q = 0; q < 4; q++) av[q] = mb4[q * 256 + tid];

    unsigned m16 = 0;
#pragma unroll
    for (int q = 0; q < 4; q++) {
        if (av[q].x > 0.5f) m16 |= 1u << (4 * q + 0);
        if (av[q].y > 0.5f) m16 |= 1u << (4 * q + 1);
        if (av[q].z > 0.5f) m16 |= 1u << (4 * q + 2);
        if (av[q].w > 0.5f) m16 |= 1u << (4 * q + 3);
    }
    {
        int cnt = __popc(m16);
        int scan = cnt;
#pragma unroll
        for (int o = 1; o < 32; o <<= 1) {
            int u = __shfl_up_sync(0xffffffffu, scan, o);
            if (lane >= o) scan += u;
        }
        if (lane == 31) wcnt[wid] = scan;
        __syncthreads();
        if (wid == 0 && lane < 8) {
            int c = wcnt[lane];
            int sc2 = c;
#pragma unroll
            for (int o = 1; o < 8; o <<= 1) {
                int u = __shfl_up_sync(0xffu, sc2, o);
                if (lane >= o) sc2 += u;
            }
            woff[lane] = sc2 - c;
            if (lane == 7) s_count = sc2;
        }
        __syncthreads();
        int pos = woff[wid] + scan - cnt;
        unsigned m = m16;
        while (m) {
            int b = __ffs(m) - 1;
            m &= m - 1;
            nbr[pos++] = (unsigned short)((b >> 2) * 1024 + tid * 4 + (b & 3));
        }
    }
    __syncthreads();   // nbr/zsi/sm/sl visible; maskbuf reads done -> ubuf reusable as szc
    const int count = s_count;
    const float inv_sqrt_s = rsqrtf((float)SS);
    float* szc = ubuf;

    // roles
    const int r3 = lane >> 3;          // gather: head of this lane
    const int q8 = lane & 7;           // gather: float4 slot within row
    const float4 zr = *(const float4*)(zsi + r3 * 32 + q8 * 4);   // fixed per lane
    const int jl2  = tid >> 2;         // softmax: neighbor slot
    const int h2   = tid & 3;          // softmax: head
    const int ak   = (tid >> 5) & 3;   // accumulate: (head, s, half)
    const int as   = tid & 31;
    const int half = tid >> 7;
    float accR = 0.f;

    // ---- phase B ----
    for (int c0 = 0; c0 < count; c0 += CHUNK) {
        const int clen = min(CHUNK, count - c0);

        // 1. cooperative gather + in-flight scores.
        //    warp-iteration = one neighbor j: 4 head-rows x 128B, 8 lanes per row.
        float mrun = NEG_INF;
#pragma unroll
        for (int it = 0; it < 8; it++) {
            int jl = (wid << 3) + it;
            if (jl < clen) {                       // warp-uniform branch
                int j = nbr[c0 + jl];
                const float4* zp = (const float4*)(g_Z + ((size_t)r3 * NN + j) * SS) + q8;
                float4 v = __ldg(zp);
                *(float4*)(szc + jl * ZROW + r3 * 32 + q8 * 4) = v;
                float pt = v.x * zr.x + v.y * zr.y + v.z * zr.z + v.w * zr.w;
                pt += __shfl_xor_sync(0xffffffffu, pt, 1);
                pt += __shfl_xor_sync(0xffffffffu, pt, 2);
                pt += __shfl_xor_sync(0xffffffffu, pt, 4);
                float sval = pt * inv_sqrt_s;
                if (q8 == 0) sc[r3][jl] = sval;
                mrun = fmaxf(mrun, sval);
            }
        }
        if (q8 == 0) wmax[wid * 4 + r3] = mrun;
        __syncthreads();                                   // (1)

        // 2. softmax state update
        if (tid < 4) {
            float cm = wmax[tid];
#pragma unroll
            for (int w = 1; w < 8; w++) cm = fmaxf(cm, wmax[w * 4 + tid]);
            float mo = sm[tid];
            float mn = fmaxf(mo, cm);
            float sca = (mo < -1e37f) ? 0.f : __expf(mo - mn);
            sm[tid] = mn; sscale[tid] = sca; sl[tid] *= sca;
        }
        __syncthreads();                                   // (2)

        // 3. exponentiate + per-head partial sums
        float p = 0.f;
        if (jl2 < clen) {
            p = __expf(sc[h2][jl2] - sm[h2]);
            sc[h2][jl2] = p;
        }
        float ps = p;
        ps += __shfl_xor_sync(0xffffffffu, ps, 16);
        ps += __shfl_xor_sync(0xffffffffu, ps, 8);
        ps += __shfl_xor_sync(0xffffffffu, ps, 4);
        if (lane < 4) wred[wid * 4 + lane] = ps;
        accR *= sscale[ak];
        __syncthreads();                                   // (3)

        // 4. finalize l; accumulate outputs from smem cache (even/odd halves)
        if (tid < 4) {
            float a2 = sl[tid];
#pragma unroll
            for (int w = 0; w < 8; w++) a2 += wred[w * 4 + tid];
            sl[tid] = a2;
        }
        {
            const float* zb = szc + ak * 32 + as;
            int t = half;
            for (; t + 2 < clen; t += 4) {
                float v0 = zb[t * ZROW];
                float v1 = zb[(t + 2) * ZROW];
                accR += sc[ak][t] * v0 + sc[ak][t + 2] * v1;
            }
            for (; t < clen; t += 2)
                accR += sc[ak][t] * zb[t * ZROW];
        }
        __syncthreads();                                   // (4)
    }

    if (half == 1) so_odd[tid - 128] = accR;
    __syncthreads();
    if (half == 0)
        g_O[(size_t)i * KS + tid] = (accR + so_odd[tid]) / sl[ak];
}

// ---------------- kernel 3: projection + epilogue (+ folded orth loss blocks) -------
__global__ __launch_bounds__(256) void k_proj(const float* __restrict__ H,
                                              const float* __restrict__ thr,
                                              float* __restrict__ out) {
    const int tid = threadIdx.x;

    if (blockIdx.x >= NPROJ) {
        // ---- orthogonality pair block ----
        const int pk[10] = {0,0,0,0,1,1,1,2,2,3};
        const int pl[10] = {0,1,2,3,1,2,3,2,3,3};
        const int pair = blockIdx.x - NPROJ;
        const int kk = pk[pair], ll = pl[pair];

        __shared__ float tA[32 * 33];
        __shared__ float tB[32 * 33];
        __shared__ float ws[8];

        const int b = tid & 31;
        const int a4 = tid >> 5;
        float c[4] = {0.f, 0.f, 0.f, 0.f};

        for (int d0 = 0; d0 < DD; d0 += 32) {
#pragma unroll
            for (int m = 0; m < 4; m++) {
                int idx = m * 256 + tid;
                int r = idx >> 5, cc = idx & 31;
                tA[r * 33 + cc] = g_Ut[(kk * SS + r) * DD + d0 + cc];
                tB[r * 33 + cc] = g_Ut[(ll * SS + r) * DD + d0 + cc];
            }
            __syncthreads();
#pragma unroll
            for (int ai = 0; ai < 4; ai++) {
                int a = a4 + ai * 8;
                float cv = c[ai];
#pragma unroll
                for (int dc = 0; dc < 32; dc++)
                    cv += tA[a * 33 + dc] * tB[b * 33 + dc];
                c[ai] = cv;
            }
            __syncthreads();
        }

        float val = 0.f;
#pragma unroll
        for (int ai = 0; ai < 4; ai++) {
            int a = a4 + ai * 8;
            float e = c[ai];
            if (kk == ll && a == b) e -= 1.f;
            val += e * e;
        }
#pragma unroll
        for (int o = 16; o > 0; o >>= 1) val += __shfl_xor_sync(0xffffffffu, val, o);
        if ((tid & 31) == 0) ws[tid >> 5] = val;
        __syncthreads();
        if (tid == 0) {
            float v = 0.f;
            for (int w = 0; w < 8; w++) v += ws[w];
            g_orth_partial[pair] = v;
        }
        return;
    }

    // ---- projection block: 8 rows ----
    __shared__ float sO[8 * KS];             // 4 KB, [r][t]
    const int r0 = blockIdx.x * 8;

    ((float4*)sO)[tid] = ((const float4*)(g_O + (size_t)r0 * KS))[tid];

    const int d = tid;
    float hreg[8];
#pragma unroll
    for (int r = 0; r < 8; r++) hreg[r] = H[(size_t)(r0 + r) * DD + d];
    const float tthr = thr[d];
    __syncthreads();

    float acc[8];
#pragma unroll
    for (int r = 0; r < 8; r++) acc[r] = 0.f;

    const float4* Uv  = (const float4*)g_Ut4;   // [t4*DD + d] -> 4 t's
    const float4* sOv = (const float4*)sO;      // [r*32 + t4]
#pragma unroll 4
    for (int t4 = 0; t4 < KS / 4; t4++) {
        float4 u = __ldg(Uv + t4 * DD + d);
#pragma unroll
        for (int r = 0; r < 8; r++) {
            float4 pv = sOv[r * 32 + t4];
            acc[r] += pv.x * u.x + pv.y * u.y + pv.z * u.z + pv.w * u.w;
        }
    }

#pragma unroll
    for (int r = 0; r < 8; r++) {
        float h = hreg[r] + ETA * acc[r];
        float a = fabsf(h) - tthr;
        out[(size_t)(r0 + r) * DD + d] = (a > 0.f) ? copysignf(a, h) : 0.f;
    }
}

__global__ void k_orth_sum(float* __restrict__ out) {
    float s = 0.f;
    for (int i = 0; i < 10; i++) s += g_orth_partial[i];
    out[(size_t)NN * DD] = s;
}

// ---------------- launch ----------------
extern "C" void kernel_launch(void* const* d_in, const int* in_sizes, int n_in,
                              void* d_out, int out_size) {
    const float* H   = (const float*)d_in[0];
    const float* adj = (const float*)d_in[1];
    const float* U   = (const float*)d_in[2];
    const float* lp  = (const float*)d_in[3];
    const float* thr = (const float*)d_in[4];
    float* out = (float*)d_out;

    const int need_orth = (out_size > NN * DD);

    k_Z<<<NN / 8, 128>>>(H, U);
    k_attn<<<NN, 256>>>(adj, lp);
    k_proj<<<NPROJ + (need_orth ? 10 : 0), 256>>>(H, thr, out);
    if (need_orth) k_orth_sum<<<1, 1>>>(out);
}

// round 13
// speedup vs baseline: 2.2567x; 1.0619x over previous
#include <cuda_runtime.h>
#include <math.h>

#define NN 4096
#define DD 256
#define SS 32
#define KK 4
#define KS (KK*SS)      // 128
#define CHUNK 64
#define ZROW 132        // szc row stride (floats): 128 data + 4 pad; accumulate reads conflict-free
#define ETA 0.5f
#define NPROJ (NN/8)    // 512 projection blocks

// ---------------- device scratch (no allocations allowed) ----------------
__device__ float g_Z[KK * NN * SS];    // Z[k][n][s], 2 MB
__device__ float g_Ut[KS * DD];        // Ut[t][d] (orth loss)
__device__ float g_Ut4[KS * DD];       // packed: [(t>>2)*DD + d]*4 + (t&3) (proj GEMM)
__device__ float g_O[NN * KS];         // normalized per-head outputs, 2 MB
__device__ float g_orth_partial[10];
__device__ int   g_orth_count;

// ---------------- mbarrier / bulk-copy helpers ----------------
__device__ __forceinline__ unsigned smem_u32(const void* p) {
    return (unsigned)__cvta_generic_to_shared(p);
}
__device__ __forceinline__ void mbar_init(unsigned addr, unsigned count) {
    asm volatile("mbarrier.init.shared.b64 [%0], %1;" :: "r"(addr), "r"(count) : "memory");
}
__device__ __forceinline__ void mbar_expect_tx(unsigned addr, unsigned bytes) {
    asm volatile("mbarrier.arrive.expect_tx.shared.b64 _, [%0], %1;"
                 :: "r"(addr), "r"(bytes) : "memory");
}
__device__ __forceinline__ void bulk_ld(unsigned dst, const void* src, unsigned bytes, unsigned mbar) {
    asm volatile("cp.async.bulk.shared::cta.global.mbarrier::complete_tx::bytes [%0], [%1], %2, [%3];"
                 :: "r"(dst), "l"(src), "r"(bytes), "r"(mbar) : "memory");
}
__device__ __forceinline__ void mbar_wait(unsigned addr, unsigned parity) {
    asm volatile(
        "{\n\t.reg .pred P1;\n"
        "WAIT_%=:\n\t"
        "mbarrier.try_wait.parity.acquire.cta.shared::cta.b64 P1, [%0], %1, 0x989680;\n\t"
        "@P1 bra DONE_%=;\n\t"
        "bra WAIT_%=;\n"
        "DONE_%=:\n\t}"
        :: "r"(addr), "r"(parity) : "memory");
}

// ---------------- kernel 1: Z = H @ U  (+ folded transposes, counter reset) --------
// grid 512 blocks x 128 threads; 8 rows per block; thread = one (k,s) column.
__global__ __launch_bounds__(128) void k_Z(const float* __restrict__ H,
                                           const float* __restrict__ U) {
    __shared__ float Hs[8 * DD];           // 8 KB
    const int row0 = blockIdx.x * 8;
    const int tid  = threadIdx.x;

    if (blockIdx.x == 0 && tid == 0) g_orth_count = 0;

    // folded transpose: 64 U elements per block -> g_Ut and g_Ut4
    if (tid < 64) {
        int e = blockIdx.x * 64 + tid;     // e < 32768
        int k = e / (DD * SS);
        int r = e % (DD * SS);
        int d = r / SS;
        int s = r % SS;
        float v = U[e];
        int t = k * SS + s;
        g_Ut[t * DD + d] = v;
        g_Ut4[((t >> 2) * DD + d) * 4 + (t & 3)] = v;
    }

    const float4* Hg = (const float4*)(H + (size_t)row0 * DD);
    float4* Hs4 = (float4*)Hs;
    for (int idx = tid; idx < 8 * DD / 4; idx += 128) Hs4[idx] = Hg[idx];
    __syncthreads();

    const int k = tid >> 5, s = tid & 31;
    float acc[8];
#pragma unroll
    for (int r = 0; r < 8; r++) acc[r] = 0.f;

    const float* Uk = U + (size_t)k * DD * SS + s;   // lanes coalesce per d
#pragma unroll 4
    for (int d = 0; d < DD; d++) {
        float u = __ldg(Uk + d * SS);
#pragma unroll
        for (int r = 0; r < 8; r++) acc[r] += Hs[r * DD + d] * u;
    }
#pragma unroll
    for (int r = 0; r < 8; r++)
        g_Z[((size_t)k * NN + row0 + r) * SS + s] = acc[r];
}

// ---------------- kernel 2: per-row sparse flash attention, 4 heads at once ----------
// grid = 4096 blocks, 256 threads, 5 blocks/SM. TMA mask; cooperative gather;
// softmax state in registers (redundant per-thread) -> 3 barriers per chunk.
__global__ __launch_bounds__(256, 5) void k_attn(const float* __restrict__ adj,
                                                 const float* __restrict__ lp) {
    const int i    = blockIdx.x;
    const int tid  = threadIdx.x;
    const int wid  = tid >> 5, lane = tid & 31;

    __shared__ __align__(16) float ubuf[CHUNK * ZROW];  // 33792 B: maskbuf (16KB) then szc
    __shared__ unsigned short nbr[NN];                  // 8 KB
    __shared__ float sc[KK][68];                        // scores/probs (padded)
    __shared__ float so_odd[KS];
    __shared__ float zsi[KS];
    __shared__ float wred[8 * 4];
    __shared__ float wmax[8 * 4];
    __shared__ int wcnt[8], woff[8];
    __shared__ int s_count;
    __shared__ __align__(8) unsigned long long mbar_store;

    const float NEG_INF = __int_as_float(0xff800000);
    const unsigned mb  = smem_u32(&mbar_store);
    const unsigned ubA = smem_u32(ubuf);

    if (tid == 0) mbar_init(mb, 1);
    __syncthreads();
    if (tid == 0) {
        mbar_expect_tx(mb, NN * 4);                     // 16384 bytes
        bulk_ld(ubA, adj + (size_t)i * NN, NN * 4, mb);
    }

    // init overlaps the bulk copy
    if (tid < KS) {
        float z = g_Z[((size_t)(tid >> 5) * NN + i) * SS + (tid & 31)];
        zsi[tid] = z * __expf(lp[tid]);
    }

    mbar_wait(mb, 0);

    // ---- phase A: compaction from smem mask ----
    float4 av[4];
    const float4* mb4 = (const float4*)ubuf;
#pragma unroll
    for (int q = 0; q < 4; q++) av[q] = mb4[q * 256 + tid];

    unsigned m16 = 0;
#pragma unroll
    for (int q = 0; q < 4; q++) {
        if (av[q].x > 0.5f) m16 |= 1u << (4 * q + 0);
        if (av[q].y > 0.5f) m16 |= 1u << (4 * q + 1);
        if (av[q].z > 0.5f) m16 |= 1u << (4 * q + 2);
        if (av[q].w > 0.5f) m16 |= 1u << (4 * q + 3);
    }
    {
        int cnt = __popc(m16);
        int scan = cnt;
#pragma unroll
        for (int o = 1; o < 32; o <<= 1) {
            int u = __shfl_up_sync(0xffffffffu, scan, o);
            if (lane >= o) scan += u;
        }
        if (lane == 31) wcnt[wid] = scan;
        __syncthreads();
        if (wid == 0 && lane < 8) {
            int c = wcnt[lane];
            int sc2 = c;
#pragma unroll
            for (int o = 1; o < 8; o <<= 1) {
                int u = __shfl_up_sync(0xffu, sc2, o);
                if (lane >= o) sc2 += u;
            }
            woff[lane] = sc2 - c;
            if (lane == 7) s_count = sc2;
        }
        __syncthreads();
        int pos = woff[wid] + scan - cnt;
        unsigned m = m16;
        while (m) {
            int b = __ffs(m) - 1;
            m &= m - 1;
            nbr[pos++] = (unsigned short)((b >> 2) * 1024 + tid * 4 + (b & 3));
        }
    }
    __syncthreads();   // nbr/zsi visible; maskbuf reads done -> ubuf reusable as szc
    const int count = s_count;
    const float inv_sqrt_s = rsqrtf((float)SS);
    float* szc = ubuf;

    // roles
    const int r3 = lane >> 3;          // gather: head of this lane
    const int q8 = lane & 7;           // gather: float4 slot within row
    const float4 zr = *(const float4*)(zsi + r3 * 32 + q8 * 4);
    const int jl2  = tid >> 2;         // softmax: neighbor slot (owner of sc[h2][jl2])
    const int h2   = tid & 3;          // softmax: head
    const int ak   = (tid >> 5) & 3;   // accumulate: (head, s, half)
    const int as   = tid & 31;
    const int half = tid >> 7;

    // per-thread softmax state (redundant across owners; identical updates)
    float m_h2 = NEG_INF, m_ak = NEG_INF, l_run = 0.f, accR = 0.f;

    // ---- phase B ----
    for (int c0 = 0; c0 < count; c0 += CHUNK) {
        const int clen = min(CHUNK, count - c0);

        // 1. cooperative gather + in-flight scores.
        float mrun = NEG_INF;
#pragma unroll
        for (int it = 0; it < 8; it++) {
            int jl = (wid << 3) + it;
            if (jl < clen) {                       // warp-uniform branch
                int j = nbr[c0 + jl];
                const float4* zp = (const float4*)(g_Z + ((size_t)r3 * NN + j) * SS) + q8;
                float4 v = __ldg(zp);
                *(float4*)(szc + jl * ZROW + r3 * 32 + q8 * 4) = v;
                float pt = v.x * zr.x + v.y * zr.y + v.z * zr.z + v.w * zr.w;
                pt += __shfl_xor_sync(0xffffffffu, pt, 1);
                pt += __shfl_xor_sync(0xffffffffu, pt, 2);
                pt += __shfl_xor_sync(0xffffffffu, pt, 4);
                float sval = pt * inv_sqrt_s;
                if (q8 == 0) sc[r3][jl] = sval;
                mrun = fmaxf(mrun, sval);
            }
        }
        if (q8 == 0) wmax[wid * 4 + r3] = mrun;
        __syncthreads();                                   // (1)

        // 2. all threads: redundant softmax-state update for their roles
        float c2 = wmax[h2], ca = wmax[ak];
#pragma unroll
        for (int w = 1; w < 8; w++) {
            c2 = fmaxf(c2, wmax[w * 4 + h2]);
            ca = fmaxf(ca, wmax[w * 4 + ak]);
        }
        float mn2 = fmaxf(m_h2, c2);
        float mna = fmaxf(m_ak, ca);
        float sca = (m_ak < -1e37f) ? 0.f : __expf(m_ak - mna);
        m_h2 = mn2; m_ak = mna;

        float p = 0.f;
        if (jl2 < clen) {
            p = __expf(sc[h2][jl2] - mn2);   // slot (h2, jl2) uniquely owned by this thread
            sc[h2][jl2] = p;
        }
        float ps = p;
        ps += __shfl_xor_sync(0xffffffffu, ps, 16);
        ps += __shfl_xor_sync(0xffffffffu, ps, 8);
        ps += __shfl_xor_sync(0xffffffffu, ps, 4);
        if (lane < 4) wred[wid * 4 + lane] = ps;
        accR *= sca;
        __syncthreads();                                   // (2)

        // 3. l update (fixed order) + accumulate from smem cache (even/odd halves)
        float lsum = 0.f;
#pragma unroll
        for (int w = 0; w < 8; w++) lsum += wred[w * 4 + ak];
        l_run = l_run * sca + lsum;
        {
            const float* zb = szc + ak * 32 + as;
            int t = half;
            for (; t + 2 < clen; t += 4) {
                float v0 = zb[t * ZROW];
                float v1 = zb[(t + 2) * ZROW];
                accR += sc[ak][t] * v0 + sc[ak][t + 2] * v1;
            }
            for (; t < clen; t += 2)
                accR += sc[ak][t] * zb[t * ZROW];
        }
        __syncthreads();                                   // (3) protects sc/szc/wmax/wred
    }

    if (half == 1) so_odd[tid - 128] = accR;
    __syncthreads();
    if (half == 0)
        g_O[(size_t)i * KS + tid] = (accR + so_odd[tid]) / l_run;
}

// ---------------- kernel 3: projection + epilogue (+ orth blocks FIRST) -------------
__global__ __launch_bounds__(256) void k_proj(const float* __restrict__ H,
                                              const float* __restrict__ thr,
                                              float* __restrict__ out,
                                              int need_orth) {
    const int tid = threadIdx.x;

    if (need_orth && blockIdx.x < 10) {
        // ---- orthogonality pair block (runs in wave 1) ----
        const int pk[10] = {0,0,0,0,1,1,1,2,2,3};
        const int pl[10] = {0,1,2,3,1,2,3,2,3,3};
        const int pair = blockIdx.x;
        const int kk = pk[pair], ll = pl[pair];

        __shared__ float tA[32 * 33];
        __shared__ float tB[32 * 33];
        __shared__ float ws[8];

        const int b = tid & 31;
        const int a4 = tid >> 5;
        float c[4] = {0.f, 0.f, 0.f, 0.f};

        for (int d0 = 0; d0 < DD; d0 += 32) {
#pragma unroll
            for (int m = 0; m < 4; m++) {
                int idx = m * 256 + tid;
                int r = idx >> 5, cc = idx & 31;
                tA[r * 33 + cc] = g_Ut[(kk * SS + r) * DD + d0 + cc];
                tB[r * 33 + cc] = g_Ut[(ll * SS + r) * DD + d0 + cc];
            }
            __syncthreads();
#pragma unroll
            for (int ai = 0; ai < 4; ai++) {
                int a = a4 + ai * 8;
                float cv = c[ai];
#pragma unroll
                for (int dc = 0; dc < 32; dc++)
                    cv += tA[a * 33 + dc] * tB[b * 33 + dc];
                c[ai] = cv;
            }
            __syncthreads();
        }

        float val = 0.f;
#pragma unroll
        for (int ai = 0; ai < 4; ai++) {
            int a = a4 + ai * 8;
            float e = c[ai];
            if (kk == ll && a == b) e -= 1.f;
            val += e * e;
        }
#pragma unroll
        for (int o = 16; o > 0; o >>= 1) val += __shfl_xor_sync(0xffffffffu, val, o);
        if ((tid & 31) == 0) ws[tid >> 5] = val;
        __syncthreads();
        if (tid == 0) {
            float v = 0.f;
            for (int w = 0; w < 8; w++) v += ws[w];
            g_orth_partial[pair] = v;
            __threadfence();
            int done = atomicAdd(&g_orth_count, 1);
            if (done == 9) {                 // last pair block: fixed-order final sum
                float s = 0.f;
                for (int q = 0; q < 10; q++) s += g_orth_partial[q];
                out[(size_t)NN * DD] = s;
            }
        }
        return;
    }

    // ---- projection block: 8 rows ----
    __shared__ float sO[8 * KS];             // 4 KB, [r][t]
    const int r0 = (need_orth ? (blockIdx.x - 10) : blockIdx.x) * 8;

    ((float4*)sO)[tid] = ((const float4*)(g_O + (size_t)r0 * KS))[tid];

    const int d = tid;
    float hreg[8];
#pragma unroll
    for (int r = 0; r < 8; r++) hreg[r] = H[(size_t)(r0 + r) * DD + d];
    const float tthr = thr[d];
    __syncthreads();

    float acc[8];
#pragma unroll
    for (int r = 0; r < 8; r++) acc[r] = 0.f;

    const float4* Uv  = (const float4*)g_Ut4;   // [t4*DD + d] -> 4 t's
    const float4* sOv = (const float4*)sO;      // [r*32 + t4]
#pragma unroll 4
    for (int t4 = 0; t4 < KS / 4; t4++) {
        float4 u = __ldg(Uv + t4 * DD + d);
#pragma unroll
        for (int r = 0; r < 8; r++) {
            float4 pv = sOv[r * 32 + t4];
            acc[r] += pv.x * u.x + pv.y * u.y + pv.z * u.z + pv.w * u.w;
        }
    }

#pragma unroll
    for (int r = 0; r < 8; r++) {
        float h = hreg[r] + ETA * acc[r];
        float a = fabsf(h) - tthr;
        out[(size_t)(r0 + r) * DD + d] = (a > 0.f) ? copysignf(a, h) : 0.f;
    }
}

// ---------------- launch ----------------
extern "C" void kernel_launch(void* const* d_in, const int* in_sizes, int n_in,
                              void* d_out, int out_size) {
    const float* H   = (const float*)d_in[0];
    const float* adj = (const float*)d_in[1];
    const float* U   = (const float*)d_in[2];
    const float* lp  = (const float*)d_in[3];
    const float* thr = (const float*)d_in[4];
    float* out = (float*)d_out;

    const int need_orth = (out_size > NN * DD) ? 1 : 0;

    k_Z<<<NN / 8, 128>>>(H, U);
    k_attn<<<NN, 256>>>(adj, lp);
    k_proj<<<NPROJ + (need_orth ? 10 : 0), 256>>>(H, thr, out, need_orth);
}

// round 14
// speedup vs baseline: 2.4296x; 1.0766x over previous
#include <cuda_runtime.h>
#include <math.h>

#define NN 4096
#define DD 256
#define SS 32
#define KK 4
#define KS (KK*SS)      // 128
#define CHUNK 64
#define ZROW 132        // szc row stride (floats): 128 data + 4 pad; accumulate reads conflict-free
#define ETA 0.5f
#define NPROJ (NN/8)    // 512 projection blocks

// ---------------- device scratch (no allocations allowed) ----------------
__device__ float g_Z[KK * NN * SS];    // Z[k][n][s], 2 MB
__device__ float g_Ut[KS * DD];        // Ut[t][d] (orth loss)
__device__ float g_Ut4[KS * DD];       // packed: [(t>>2)*DD + d]*4 + (t&3) (proj GEMM)
__device__ float g_O[NN * KS];         // normalized per-head outputs, 2 MB
__device__ float g_orth_partial[10];
__device__ int   g_orth_count;

// ---------------- mbarrier / bulk-copy helpers ----------------
__device__ __forceinline__ unsigned smem_u32(const void* p) {
    return (unsigned)__cvta_generic_to_shared(p);
}
__device__ __forceinline__ void mbar_init(unsigned addr, unsigned count) {
    asm volatile("mbarrier.init.shared.b64 [%0], %1;" :: "r"(addr), "r"(count) : "memory");
}
__device__ __forceinline__ void mbar_expect_tx(unsigned addr, unsigned bytes) {
    asm volatile("mbarrier.arrive.expect_tx.shared.b64 _, [%0], %1;"
                 :: "r"(addr), "r"(bytes) : "memory");
}
__device__ __forceinline__ void bulk_ld(unsigned dst, const void* src, unsigned bytes, unsigned mbar) {
    asm volatile("cp.async.bulk.shared::cta.global.mbarrier::complete_tx::bytes [%0], [%1], %2, [%3];"
                 :: "r"(dst), "l"(src), "r"(bytes), "r"(mbar) : "memory");
}
__device__ __forceinline__ void mbar_wait(unsigned addr, unsigned parity) {
    asm volatile(
        "{\n\t.reg .pred P1;\n"
        "WAIT_%=:\n\t"
        "mbarrier.try_wait.parity.acquire.cta.shared::cta.b64 P1, [%0], %1, 0x989680;\n\t"
        "@P1 bra DONE_%=;\n\t"
        "bra WAIT_%=;\n"
        "DONE_%=:\n\t}"
        :: "r"(addr), "r"(parity) : "memory");
}

// ---------------- kernel 1: Z = H @ U  (split-K over d, 2 groups) -------------------
// grid 512 blocks x 256 threads; 8 rows per block.
// Group g (128 threads = one (k,s) column each) reduces d in [128g, 128g+128);
// deterministic fixed-order combine g0+g1 afterwards.
__global__ __launch_bounds__(256) void k_Z(const float* __restrict__ H,
                                           const float* __restrict__ U) {
    __shared__ float Hs[8 * DD];           // 8 KB
    __shared__ float red[8 * KS];          // 4 KB staging (group-1 partials)
    const int row0 = blockIdx.x * 8;
    const int tid  = threadIdx.x;
    const int g    = tid >> 7;             // d-group 0/1
    const int t    = tid & 127;            // (k,s) column
    const int k    = t >> 5, s = t & 31;

    if (blockIdx.x == 0 && tid == 0) g_orth_count = 0;

    // folded transpose: 64 U elements per block -> g_Ut and g_Ut4
    if (tid < 64) {
        int e = blockIdx.x * 64 + tid;     // e < 32768
        int kk = e / (DD * SS);
        int r = e % (DD * SS);
        int d = r / SS;
        int ss = r % SS;
        float v = U[e];
        int tt = kk * SS + ss;
        g_Ut[tt * DD + d] = v;
        g_Ut4[((tt >> 2) * DD + d) * 4 + (tt & 3)] = v;
    }

    const float4* Hg = (const float4*)(H + (size_t)row0 * DD);
    float4* Hs4 = (float4*)Hs;
    for (int idx = tid; idx < 8 * DD / 4; idx += 256) Hs4[idx] = Hg[idx];
    __syncthreads();

    float acc[8];
#pragma unroll
    for (int r = 0; r < 8; r++) acc[r] = 0.f;

    const float* Uk = U + (size_t)k * DD * SS + (size_t)g * 128 * SS + s;
    const float* Hb = Hs + g * 128;
#pragma unroll 8
    for (int d = 0; d < 128; d++) {
        float u = __ldg(Uk + d * SS);
#pragma unroll
        for (int r = 0; r < 8; r++) acc[r] += Hb[r * DD + d] * u;
    }

    if (g == 1) {
#pragma unroll
        for (int r = 0; r < 8; r++) red[r * KS + t] = acc[r];
    }
    __syncthreads();
    if (g == 0) {
#pragma unroll
        for (int r = 0; r < 8; r++)
            g_Z[((size_t)k * NN + row0 + r) * SS + s] = acc[r] + red[r * KS + t];
    }
}

// ---------------- kernel 2: per-row sparse flash attention, 4 heads at once ----------
// grid = 4096 blocks, 256 threads, 5 blocks/SM. TMA mask; cooperative gather;
// softmax state in registers (redundant per-thread) -> 3 barriers per chunk.
__global__ __launch_bounds__(256, 5) void k_attn(const float* __restrict__ adj,
                                                 const float* __restrict__ lp) {
    const int i    = blockIdx.x;
    const int tid  = threadIdx.x;
    const int wid  = tid >> 5, lane = tid & 31;

    __shared__ __align__(16) float ubuf[CHUNK * ZROW];  // 33792 B: maskbuf (16KB) then szc
    __shared__ unsigned short nbr[NN];                  // 8 KB
    __shared__ float sc[KK][68];                        // scores/probs (padded)
    __shared__ float so_odd[KS];
    __shared__ float zsi[KS];
    __shared__ float wred[8 * 4];
    __shared__ float wmax[8 * 4];
    __shared__ int wcnt[8], woff[8];
    __shared__ int s_count;
    __shared__ __align__(8) unsigned long long mbar_store;

    const float NEG_INF = __int_as_float(0xff800000);
    const unsigned mb  = smem_u32(&mbar_store);
    const unsigned ubA = smem_u32(ubuf);

    if (tid == 0) mbar_init(mb, 1);
    __syncthreads();
    if (tid == 0) {
        mbar_expect_tx(mb, NN * 4);                     // 16384 bytes
        bulk_ld(ubA, adj + (size_t)i * NN, NN * 4, mb);
    }

    // init overlaps the bulk copy
    if (tid < KS) {
        float z = g_Z[((size_t)(tid >> 5) * NN + i) * SS + (tid & 31)];
        zsi[tid] = z * __expf(lp[tid]);
    }

    mbar_wait(mb, 0);

    // ---- phase A: compaction from smem mask ----
    float4 av[4];
    const float4* mb4 = (const float4*)ubuf;
#pragma unroll
    for (int q = 0; q < 4; q++) av[q] = mb4[q * 256 + tid];

    unsigned m16 = 0;
#pragma unroll
    for (int q = 0; q < 4; q++) {
        if (av[q].x > 0.5f) m16 |= 1u << (4 * q + 0);
        if (av[q].y > 0.5f) m16 |= 1u << (4 * q + 1);
        if (av[q].z > 0.5f) m16 |= 1u << (4 * q + 2);
        if (av[q].w > 0.5f) m16 |= 1u << (4 * q + 3);
    }
    {
        int cnt = __popc(m16);
        int scan = cnt;
#pragma unroll
        for (int o = 1; o < 32; o <<= 1) {
            int u = __shfl_up_sync(0xffffffffu, scan, o);
            if (lane >= o) scan += u;
        }
        if (lane == 31) wcnt[wid] = scan;
        __syncthreads();
        if (wid == 0 && lane < 8) {
            int c = wcnt[lane];
            int sc2 = c;
#pragma unroll
            for (int o = 1; o < 8; o <<= 1) {
                int u = __shfl_up_sync(0xffu, sc2, o);
                if (lane >= o) sc2 += u;
            }
            woff[lane] = sc2 - c;
            if (lane == 7) s_count = sc2;
        }
        __syncthreads();
        int pos = woff[wid] + scan - cnt;
        unsigned m = m16;
        while (m) {
            int b = __ffs(m) - 1;
            m &= m - 1;
            nbr[pos++] = (unsigned short)((b >> 2) * 1024 + tid * 4 + (b & 3));
        }
    }
    __syncthreads();   // nbr/zsi visible; maskbuf reads done -> ubuf reusable as szc
    const int count = s_count;
    const float inv_sqrt_s = rsqrtf((float)SS);
    float* szc = ubuf;

    // roles
    const int r3 = lane >> 3;          // gather: head of this lane
    const int q8 = lane & 7;           // gather: float4 slot within row
    const float4 zr = *(const float4*)(zsi + r3 * 32 + q8 * 4);
    const int jl2  = tid >> 2;         // softmax: neighbor slot (owner of sc[h2][jl2])
    const int h2   = tid & 3;          // softmax: head
    const int ak   = (tid >> 5) & 3;   // accumulate: (head, s, half)
    const int as   = tid & 31;
    const int half = tid >> 7;

    // per-thread softmax state (redundant across owners; identical updates)
    float m_h2 = NEG_INF, m_ak = NEG_INF, l_run = 0.f, accR = 0.f;

    // ---- phase B ----
    for (int c0 = 0; c0 < count; c0 += CHUNK) {
        const int clen = min(CHUNK, count - c0);

        // 1. cooperative gather + in-flight scores.
        float mrun = NEG_INF;
#pragma unroll
        for (int it = 0; it < 8; it++) {
            int jl = (wid << 3) + it;
            if (jl < clen) {                       // warp-uniform branch
                int j = nbr[c0 + jl];
                const float4* zp = (const float4*)(g_Z + ((size_t)r3 * NN + j) * SS) + q8;
                float4 v = __ldg(zp);
                *(float4*)(szc + jl * ZROW + r3 * 32 + q8 * 4) = v;
                float pt = v.x * zr.x + v.y * zr.y + v.z * zr.z + v.w * zr.w;
                pt += __shfl_xor_sync(0xffffffffu, pt, 1);
                pt += __shfl_xor_sync(0xffffffffu, pt, 2);
                pt += __shfl_xor_sync(0xffffffffu, pt, 4);
                float sval = pt * inv_sqrt_s;
                if (q8 == 0) sc[r3][jl] = sval;
                mrun = fmaxf(mrun, sval);
            }
        }
        if (q8 == 0) wmax[wid * 4 + r3] = mrun;
        __syncthreads();                                   // (1)

        // 2. all threads: redundant softmax-state update for their roles
        float c2 = wmax[h2], ca = wmax[ak];
#pragma unroll
        for (int w = 1; w < 8; w++) {
            c2 = fmaxf(c2, wmax[w * 4 + h2]);
            ca = fmaxf(ca, wmax[w * 4 + ak]);
        }
        float mn2 = fmaxf(m_h2, c2);
        float mna = fmaxf(m_ak, ca);
        float sca = (m_ak < -1e37f) ? 0.f : __expf(m_ak - mna);
        m_h2 = mn2; m_ak = mna;

        float p = 0.f;
        if (jl2 < clen) {
            p = __expf(sc[h2][jl2] - mn2);   // slot (h2, jl2) uniquely owned by this thread
            sc[h2][jl2] = p;
        }
        float ps = p;
        ps += __shfl_xor_sync(0xffffffffu, ps, 16);
        ps += __shfl_xor_sync(0xffffffffu, ps, 8);
        ps += __shfl_xor_sync(0xffffffffu, ps, 4);
        if (lane < 4) wred[wid * 4 + lane] = ps;
        accR *= sca;
        __syncthreads();                                   // (2)

        // 3. l update (fixed order) + accumulate from smem cache (even/odd halves)
        float lsum = 0.f;
#pragma unroll
        for (int w = 0; w < 8; w++) lsum += wred[w * 4 + ak];
        l_run = l_run * sca + lsum;
        {
            const float* zb = szc + ak * 32 + as;
            int t = half;
            for (; t + 2 < clen; t += 4) {
                float v0 = zb[t * ZROW];
                float v1 = zb[(t + 2) * ZROW];
                accR += sc[ak][t] * v0 + sc[ak][t + 2] * v1;
            }
            for (; t < clen; t += 2)
                accR += sc[ak][t] * zb[t * ZROW];
        }
        __syncthreads();                                   // (3) protects sc/szc/wmax/wred
    }

    if (half == 1) so_odd[tid - 128] = accR;
    __syncthreads();
    if (half == 0)
        g_O[(size_t)i * KS + tid] = (accR + so_odd[tid]) / l_run;
}

// ---------------- kernel 3: projection + epilogue (+ orth blocks FIRST) -------------
__global__ __launch_bounds__(256) void k_proj(const float* __restrict__ H,
                                              const float* __restrict__ thr,
                                              float* __restrict__ out,
                                              int need_orth) {
    const int tid = threadIdx.x;

    if (need_orth && blockIdx.x < 10) {
        // ---- orthogonality pair block (runs in wave 1) ----
        const int pk[10] = {0,0,0,0,1,1,1,2,2,3};
        const int pl[10] = {0,1,2,3,1,2,3,2,3,3};
        const int pair = blockIdx.x;
        const int kk = pk[pair], ll = pl[pair];

        __shared__ float tA[32 * 33];
        __shared__ float tB[32 * 33];
        __shared__ float ws[8];

        const int b = tid & 31;
        const int a4 = tid >> 5;
        float c[4] = {0.f, 0.f, 0.f, 0.f};

        for (int d0 = 0; d0 < DD; d0 += 32) {
#pragma unroll
            for (int m = 0; m < 4; m++) {
                int idx = m * 256 + tid;
                int r = idx >> 5, cc = idx & 31;
                tA[r * 33 + cc] = g_Ut[(kk * SS + r) * DD + d0 + cc];
                tB[r * 33 + cc] = g_Ut[(ll * SS + r) * DD + d0 + cc];
            }
            __syncthreads();
#pragma unroll
            for (int ai = 0; ai < 4; ai++) {
                int a = a4 + ai * 8;
                float cv = c[ai];
#pragma unroll
                for (int dc = 0; dc < 32; dc++)
                    cv += tA[a * 33 + dc] * tB[b * 33 + dc];
                c[ai] = cv;
            }
            __syncthreads();
        }

        float val = 0.f;
#pragma unroll
        for (int ai = 0; ai < 4; ai++) {
            int a = a4 + ai * 8;
            float e = c[ai];
            if (kk == ll && a == b) e -= 1.f;
            val += e * e;
        }
#pragma unroll
        for (int o = 16; o > 0; o >>= 1) val += __shfl_xor_sync(0xffffffffu, val, o);
        if ((tid & 31) == 0) ws[tid >> 5] = val;
        __syncthreads();
        if (tid == 0) {
            float v = 0.f;
            for (int w = 0; w < 8; w++) v += ws[w];
            g_orth_partial[pair] = v;
            __threadfence();
            int done = atomicAdd(&g_orth_count, 1);
            if (done == 9) {                 // last pair block: fixed-order final sum
                float s = 0.f;
                for (int q = 0; q < 10; q++) s += g_orth_partial[q];
                out[(size_t)NN * DD] = s;
            }
        }
        return;
    }

    // ---- projection block: 8 rows ----
    __shared__ float sO[8 * KS];             // 4 KB, [r][t]
    const int r0 = (need_orth ? (blockIdx.x - 10) : blockIdx.x) * 8;

    ((float4*)sO)[tid] = ((const float4*)(g_O + (size_t)r0 * KS))[tid];

    const int d = tid;
    float hreg[8];
#pragma unroll
    for (int r = 0; r < 8; r++) hreg[r] = H[(size_t)(r0 + r) * DD + d];
    const float tthr = thr[d];
    __syncthreads();

    float acc[8];
#pragma unroll
    for (int r = 0; r < 8; r++) acc[r] = 0.f;

    const float4* Uv  = (const float4*)g_Ut4;   // [t4*DD + d] -> 4 t's
    const float4* sOv = (const float4*)sO;      // [r*32 + t4]
#pragma unroll 4
    for (int t4 = 0; t4 < KS / 4; t4++) {
        float4 u = __ldg(Uv + t4 * DD + d);
#pragma unroll
        for (int r = 0; r < 8; r++) {
            float4 pv = sOv[r * 32 + t4];
            acc[r] += pv.x * u.x + pv.y * u.y + pv.z * u.z + pv.w * u.w;
        }
    }

#pragma unroll
    for (int r = 0; r < 8; r++) {
        float h = hreg[r] + ETA * acc[r];
        float a = fabsf(h) - tthr;
        out[(size_t)(r0 + r) * DD + d] = (a > 0.f) ? copysignf(a, h) : 0.f;
    }
}

// ---------------- launch ----------------
extern "C" void kernel_launch(void* const* d_in, const int* in_sizes, int n_in,
                              void* d_out, int out_size) {
    const float* H   = (const float*)d_in[0];
    const float* adj = (const float*)d_in[1];
    const float* U   = (const float*)d_in[2];
    const float* lp  = (const float*)d_in[3];
    const float* thr = (const float*)d_in[4];
    float* out = (float*)d_out;

    const int need_orth = (out_size > NN * DD) ? 1 : 0;

    k_Z<<<NN / 8, 256>>>(H, U);
    k_attn<<<NN, 256>>>(adj, lp);
    k_proj<<<NPROJ + (need_orth ? 10 : 0), 256>>>(H, thr, out, need_orth);
}